// round 5
// baseline (speedup 1.0000x reference)
#include <cuda_runtime.h>
#include <cstdint>
#include <math_constants.h>

#define N_NODES 20
#define IN_DIM  9
#define HID     128
#define KNN     5
#define LN_EPS  1e-5f

__device__ __forceinline__ float gelu_exact(float x) {
    return 0.5f * x * (1.0f + erff(x * 0.70710678118654752440f));
}

// one CTA per graph, 128 threads (thread t = feature channel t)
__global__ void __launch_bounds__(128)
hbond_gnn_kernel(const float* __restrict__ x_all,
                 const float* __restrict__ w_embed,
                 const float* __restrict__ b_embed,
                 const float* __restrict__ w1,
                 const float* __restrict__ b1,
                 const float* __restrict__ w2,
                 const float* __restrict__ b2,
                 const float* __restrict__ g1,
                 const float* __restrict__ be1,
                 const float* __restrict__ g2,
                 const float* __restrict__ be2,
                 float* __restrict__ out)
{
    const int b = blockIdx.x;
    const int t = threadIdx.x;          // 0..127, feature channel

    // two 128x20 k-major tiles (rows are feature channels), reused/aliased as
    // 20x128 node-major LN staging after each GEMM.
    __shared__ __align__(16) float hkA[HID * N_NODES];   // 10240 B
    __shared__ __align__(16) float hkB[HID * N_NODES];   // 10240 B
    __shared__ float xs[N_NODES * IN_DIM];
    __shared__ int   nbrs[N_NODES * KNN];
    __shared__ float mean_s[N_NODES];
    __shared__ float rstd_s[N_NODES];

    // ---- load per-channel parameters -------------------------------------
    float we[IN_DIM];
    #pragma unroll
    for (int c = 0; c < IN_DIM; c++) we[c] = w_embed[c * HID + t];
    const float bev  = b_embed[t];
    const float b1v  = b1[t];
    const float b2v  = b2[t];
    const float g1v  = g1[t];
    const float be1v = be1[t];
    const float g2v  = g2[t];
    const float be2v = be2[t];

    // ---- load graph input into smem --------------------------------------
    const float* xg = x_all + (size_t)b * (N_NODES * IN_DIM);
    for (int idx = t; idx < N_NODES * IN_DIM; idx += 128) xs[idx] = xg[idx];
    __syncthreads();

    // ---- kNN adjacency (threads 0..19, one node each) --------------------
    if (t < N_NODES) {
        const float px = xs[t * IN_DIM + 6];
        const float py = xs[t * IN_DIM + 7];
        const float pz = xs[t * IN_DIM + 8];
        float d2[N_NODES];
        #pragma unroll
        for (int j = 0; j < N_NODES; j++) {
            float dx = px - xs[j * IN_DIM + 6];
            float dy = py - xs[j * IN_DIM + 7];
            float dz = pz - xs[j * IN_DIM + 8];
            d2[j] = fmaf(dx, dx, fmaf(dy, dy, dz * dz));
        }
        unsigned mask = 0;
        #pragma unroll
        for (int m = 0; m < KNN; m++) {
            float best = CUDART_INF_F;
            int bj = 0;
            #pragma unroll
            for (int j = 0; j < N_NODES; j++) {
                // strict < keeps the lowest index among ties (top_k semantics)
                if (!((mask >> j) & 1u) && d2[j] < best) { best = d2[j]; bj = j; }
            }
            mask |= 1u << bj;
            nbrs[t * KNN + m] = bj;
        }
    }
    __syncthreads();

    // ---- embed: h0[i][t], write own k-major row ---------------------------
    #pragma unroll
    for (int i = 0; i < N_NODES; i++) {
        float e = bev;
        #pragma unroll
        for (int c = 0; c < IN_DIM; c++) e = fmaf(xs[i * IN_DIM + c], we[c], e);
        hkA[t * N_NODES + i] = e;
    }
    // ---- gather 1: h1[i] = sum_{j in knn(i)} h0[j]  (own row only) --------
    #pragma unroll
    for (int i = 0; i < N_NODES; i++) {
        const int* nb = &nbrs[i * KNN];
        float s = hkA[t * N_NODES + nb[0]];
        s += hkA[t * N_NODES + nb[1]];
        s += hkA[t * N_NODES + nb[2]];
        s += hkA[t * N_NODES + nb[3]];
        s += hkA[t * N_NODES + nb[4]];
        hkB[t * N_NODES + i] = s;
    }
    __syncthreads();

    // ---- GEMM 1: acc[i] = sum_k h1[k][i] * w1[k][t]  (packed f32x2) ------
    unsigned long long acc[N_NODES / 2];
    #pragma unroll
    for (int p = 0; p < N_NODES / 2; p++) acc[p] = 0ull;
    {
        const float* wc = w1 + t;
        #pragma unroll 4
        for (int k = 0; k < HID; k++) {
            float wv = __ldg(wc + (k << 7));
            unsigned long long wp;
            asm("mov.b64 %0, {%1, %1};" : "=l"(wp) : "r"(__float_as_uint(wv)));
            const ulonglong2* row = reinterpret_cast<const ulonglong2*>(&hkB[k * N_NODES]);
            #pragma unroll
            for (int q = 0; q < 5; q++) {
                ulonglong2 hv = row[q];
                asm("fma.rn.f32x2 %0, %1, %2, %0;" : "+l"(acc[2 * q])     : "l"(hv.x), "l"(wp));
                asm("fma.rn.f32x2 %0, %1, %2, %0;" : "+l"(acc[2 * q + 1]) : "l"(hv.y), "l"(wp));
            }
        }
    }
    float accf[N_NODES];
    #pragma unroll
    for (int p = 0; p < N_NODES / 2; p++) {
        unsigned lo, hi;
        asm("mov.b64 {%0,%1}, %2;" : "=r"(lo), "=r"(hi) : "l"(acc[p]));
        accf[2 * p]     = __uint_as_float(lo) + b1v;
        accf[2 * p + 1] = __uint_as_float(hi) + b1v;
    }

    // ---- LN 1 stats (stage node-major into hkA, warp-parallel reduce) ----
    __syncthreads();                       // all GEMM1 reads of hkB done; hkA dead
    float* gn = hkA;
    #pragma unroll
    for (int i = 0; i < N_NODES; i++) gn[i * HID + t] = accf[i];
    __syncthreads();
    {
        const int warp = t >> 5, lane = t & 31;
        #pragma unroll
        for (int ii = 0; ii < 5; ii++) {
            const int i = warp + (ii << 2);
            float a0 = gn[i * HID + lane];
            float a1 = gn[i * HID + lane + 32];
            float a2 = gn[i * HID + lane + 64];
            float a3 = gn[i * HID + lane + 96];
            float s = (a0 + a1) + (a2 + a3);
            float q = fmaf(a0, a0, fmaf(a1, a1, fmaf(a2, a2, a3 * a3)));
            #pragma unroll
            for (int off = 16; off; off >>= 1) {
                s += __shfl_xor_sync(0xffffffffu, s, off);
                q += __shfl_xor_sync(0xffffffffu, q, off);
            }
            if (lane == 0) {
                float m = s * (1.0f / HID);
                mean_s[i] = m;
                rstd_s[i] = rsqrtf(fmaf(-m, m, q * (1.0f / HID)) + LN_EPS);
            }
        }
    }
    __syncthreads();

    // ---- normalize + gelu -> hcur regs, write k-major for gather 2 -------
    float hcur[N_NODES];
    #pragma unroll
    for (int i = 0; i < N_NODES; i++) {
        float v = (accf[i] - mean_s[i]) * rstd_s[i] * g1v + be1v;
        hcur[i] = gelu_exact(v);
        hkB[t * N_NODES + i] = hcur[i];
    }
    // ---- gather 2 (own row only) -----------------------------------------
    #pragma unroll
    for (int i = 0; i < N_NODES; i++) {
        const int* nb = &nbrs[i * KNN];
        float s = hkB[t * N_NODES + nb[0]];
        s += hkB[t * N_NODES + nb[1]];
        s += hkB[t * N_NODES + nb[2]];
        s += hkB[t * N_NODES + nb[3]];
        s += hkB[t * N_NODES + nb[4]];
        hkA[t * N_NODES + i] = s;
    }
    __syncthreads();

    // ---- GEMM 2 ----------------------------------------------------------
    #pragma unroll
    for (int p = 0; p < N_NODES / 2; p++) acc[p] = 0ull;
    {
        const float* wc = w2 + t;
        #pragma unroll 4
        for (int k = 0; k < HID; k++) {
            float wv = __ldg(wc + (k << 7));
            unsigned long long wp;
            asm("mov.b64 %0, {%1, %1};" : "=l"(wp) : "r"(__float_as_uint(wv)));
            const ulonglong2* row = reinterpret_cast<const ulonglong2*>(&hkA[k * N_NODES]);
            #pragma unroll
            for (int q = 0; q < 5; q++) {
                ulonglong2 hv = row[q];
                asm("fma.rn.f32x2 %0, %1, %2, %0;" : "+l"(acc[2 * q])     : "l"(hv.x), "l"(wp));
                asm("fma.rn.f32x2 %0, %1, %2, %0;" : "+l"(acc[2 * q + 1]) : "l"(hv.y), "l"(wp));
            }
        }
    }
    #pragma unroll
    for (int p = 0; p < N_NODES / 2; p++) {
        unsigned lo, hi;
        asm("mov.b64 {%0,%1}, %2;" : "=r"(lo), "=r"(hi) : "l"(acc[p]));
        accf[2 * p]     = __uint_as_float(lo) + b2v;
        accf[2 * p + 1] = __uint_as_float(hi) + b2v;
    }

    // ---- LN 2 stats (stage into hkB) -------------------------------------
    __syncthreads();                        // all GEMM2 reads of hkA done
    float* gn2 = hkB;
    #pragma unroll
    for (int i = 0; i < N_NODES; i++) gn2[i * HID + t] = accf[i];
    __syncthreads();
    {
        const int warp = t >> 5, lane = t & 31;
        #pragma unroll
        for (int ii = 0; ii < 5; ii++) {
            const int i = warp + (ii << 2);
            float a0 = gn2[i * HID + lane];
            float a1 = gn2[i * HID + lane + 32];
            float a2 = gn2[i * HID + lane + 64];
            float a3 = gn2[i * HID + lane + 96];
            float s = (a0 + a1) + (a2 + a3);
            float q = fmaf(a0, a0, fmaf(a1, a1, fmaf(a2, a2, a3 * a3)));
            #pragma unroll
            for (int off = 16; off; off >>= 1) {
                s += __shfl_xor_sync(0xffffffffu, s, off);
                q += __shfl_xor_sync(0xffffffffu, q, off);
            }
            if (lane == 0) {
                float m = s * (1.0f / HID);
                mean_s[i] = m;
                rstd_s[i] = rsqrtf(fmaf(-m, m, q * (1.0f / HID)) + LN_EPS);
            }
        }
    }
    __syncthreads();

    // ---- residual + gelu + max over nodes --------------------------------
    float mx = -CUDART_INF_F;
    #pragma unroll
    for (int i = 0; i < N_NODES; i++) {
        float v = (accf[i] - mean_s[i]) * rstd_s[i] * g2v + be2v;
        float f = gelu_exact(hcur[i] + v);
        mx = fmaxf(mx, f);
    }
    out[(size_t)b * HID + t] = mx;
}

extern "C" void kernel_launch(void* const* d_in, const int* in_sizes, int n_in,
                              void* d_out, int out_size)
{
    const float* x_all   = (const float*)d_in[0];
    const float* w_embed = (const float*)d_in[1];
    const float* b_embed = (const float*)d_in[2];
    const float* w1      = (const float*)d_in[3];
    const float* b1      = (const float*)d_in[4];
    const float* w2      = (const float*)d_in[5];
    const float* b2      = (const float*)d_in[6];
    const float* g1      = (const float*)d_in[7];
    const float* be1     = (const float*)d_in[8];
    const float* g2      = (const float*)d_in[9];
    const float* be2     = (const float*)d_in[10];
    float* out = (float*)d_out;

    const int B = in_sizes[0] / (N_NODES * IN_DIM);

    hbond_gnn_kernel<<<B, 128>>>(x_all, w_embed, b_embed, w1, b1, w2, b2,
                                 g1, be1, g2, be2, out);
}

// round 11
// speedup vs baseline: 2.2350x; 2.2350x over previous
#include <cuda_runtime.h>
#include <cstdint>
#include <math_constants.h>

#define N_NODES 20
#define IN_DIM  9
#define HID     128
#define KNN     5
#define LN_EPS  1e-5f

typedef unsigned long long ull;

// Precomputed folded first layer: W1c = w_embed @ w1  (9x128),
// b1c = 5*(b_embed @ w1) + b1  (adjacency rows sum to exactly KNN=5).
__device__ float W1c_g[IN_DIM * HID];
__device__ float b1c_g[HID];

__device__ __forceinline__ float gelu_exact(float x) {
    return 0.5f * x * (1.0f + erff(x * 0.70710678118654752440f));
}
__device__ __forceinline__ ull splat2(float v) {
    ull r; asm("mov.b64 %0, {%1, %1};" : "=l"(r) : "r"(__float_as_uint(v))); return r;
}
__device__ __forceinline__ ull pack2(float a, float b) {
    ull r; asm("mov.b64 %0, {%1, %2};" : "=l"(r)
               : "r"(__float_as_uint(a)), "r"(__float_as_uint(b))); return r;
}
__device__ __forceinline__ void unpack2(ull v, float& a, float& b) {
    unsigned lo, hi; asm("mov.b64 {%0,%1}, %2;" : "=r"(lo), "=r"(hi) : "l"(v));
    a = __uint_as_float(lo); b = __uint_as_float(hi);
}
#define FMA2(acc, h, w) asm("fma.rn.f32x2 %0, %1, %2, %0;" : "+l"(acc) : "l"(h), "l"(w))
#define ADD2(acc, v)    asm("add.rn.f32x2 %0, %1, %0;"     : "+l"(acc) : "l"(v))

// ---------------------------------------------------------------------------
// Prep: fold embed into GEMM1. One tiny CTA, runs once per launch.
// ---------------------------------------------------------------------------
__global__ void prep_kernel(const float* __restrict__ we, const float* __restrict__ be,
                            const float* __restrict__ w1, const float* __restrict__ b1)
{
    const int c = threadIdx.x;            // 0..127
    float acc[IN_DIM];
    #pragma unroll
    for (int q = 0; q < IN_DIM; q++) acc[q] = 0.0f;
    float bb = 0.0f;
    for (int m = 0; m < HID; m++) {
        const float w = w1[m * HID + c];
        #pragma unroll
        for (int q = 0; q < IN_DIM; q++) acc[q] = fmaf(we[q * HID + m], w, acc[q]);
        bb = fmaf(be[m], w, bb);
    }
    #pragma unroll
    for (int q = 0; q < IN_DIM; q++) W1c_g[q * HID + c] = acc[q];
    b1c_g[c] = fmaf(5.0f, bb, b1[c]);
}

// ---------------------------------------------------------------------------
// Main: one CTA per graph, 64 threads; thread t owns channels (2t, 2t+1).
// Gathers commuted to after each GEMM (adjacency acts on nodes, weights on
// channels -> they commute); gathers read node-major float2 (conflict-free).
// ---------------------------------------------------------------------------
__global__ void __launch_bounds__(64, 8)
hbond_gnn_kernel(const float* __restrict__ x_all,
                 const float* __restrict__ w2,
                 const float* __restrict__ b2,
                 const float* __restrict__ g1,
                 const float* __restrict__ be1,
                 const float* __restrict__ g2,
                 const float* __restrict__ be2,
                 float* __restrict__ out)
{
    const int b    = blockIdx.x;
    const int t    = threadIdx.x;          // 0..63
    const int warp = t >> 5, lane = t & 31;
    const int c0   = 2 * t;                // channel pair (c0, c0+1)

    __shared__ __align__(16) float nm[N_NODES * HID];    // node-major staging
    __shared__ __align__(16) float km[HID * N_NODES];    // k-major GEMM2 operand
    __shared__ __align__(16) float xk[IN_DIM * N_NODES]; // x^T (k-major, 9x20)
    __shared__ float xs[N_NODES * IN_DIM];
    __shared__ int   nbrs[N_NODES * KNN];
    __shared__ float mean_s[N_NODES];
    __shared__ float rstd_s[N_NODES];

    // ---- load graph input --------------------------------------------------
    const float* xg = x_all + (size_t)b * (N_NODES * IN_DIM);
    for (int idx = t; idx < N_NODES * IN_DIM; idx += 64) xs[idx] = xg[idx];
    __syncthreads();                                               // (1)

    // ---- transpose x to k-major --------------------------------------------
    for (int idx = t; idx < N_NODES * IN_DIM; idx += 64) {
        int i = idx / IN_DIM, q = idx % IN_DIM;
        xk[q * N_NODES + i] = xs[idx];
    }
    // ---- kNN (threads 0..19, one node each) --------------------------------
    if (t < N_NODES) {
        const float px = xs[t * IN_DIM + 6];
        const float py = xs[t * IN_DIM + 7];
        const float pz = xs[t * IN_DIM + 8];
        float d2[N_NODES];
        #pragma unroll
        for (int j = 0; j < N_NODES; j++) {
            float dx = px - xs[j * IN_DIM + 6];
            float dy = py - xs[j * IN_DIM + 7];
            float dz = pz - xs[j * IN_DIM + 8];
            d2[j] = fmaf(dx, dx, fmaf(dy, dy, dz * dz));
        }
        unsigned mask = 0;
        #pragma unroll
        for (int m = 0; m < KNN; m++) {
            float best = CUDART_INF_F; int bj = 0;
            #pragma unroll
            for (int j = 0; j < N_NODES; j++) {
                // strict < keeps lowest index among ties (top_k semantics)
                if (!((mask >> j) & 1u) && d2[j] < best) { best = d2[j]; bj = j; }
            }
            mask |= 1u << bj;
            nbrs[t * KNN + m] = bj;
        }
    }
    __syncthreads();                                               // (2)

    // ---- GEMM1 (K=9, folded embed): y = x @ W1c, channels c0,c0+1 ----------
    ull a0[N_NODES / 2], a1[N_NODES / 2];     // node-pair packed, per channel
    #pragma unroll
    for (int p = 0; p < N_NODES / 2; p++) { a0[p] = 0ull; a1[p] = 0ull; }
    #pragma unroll
    for (int q = 0; q < IN_DIM; q++) {
        const float2 w = *reinterpret_cast<const float2*>(&W1c_g[q * HID + c0]);
        const ull wp0 = splat2(w.x), wp1 = splat2(w.y);
        const ulonglong2* row = reinterpret_cast<const ulonglong2*>(&xk[q * N_NODES]);
        #pragma unroll
        for (int p = 0; p < 5; p++) {
            ulonglong2 hv = row[p];
            FMA2(a0[2 * p],     hv.x, wp0); FMA2(a0[2 * p + 1], hv.y, wp0);
            FMA2(a1[2 * p],     hv.x, wp1); FMA2(a1[2 * p + 1], hv.y, wp1);
        }
    }
    // stage y node-major as float2 {c0, c0+1}
    #pragma unroll
    for (int p = 0; p < N_NODES / 2; p++) {
        float y00, y01, y10, y11;
        unpack2(a0[p], y00, y01);   // channel c0, nodes 2p, 2p+1
        unpack2(a1[p], y10, y11);   // channel c0+1
        *reinterpret_cast<float2*>(&nm[(2 * p)     * HID + c0]) = make_float2(y00, y10);
        *reinterpret_cast<float2*>(&nm[(2 * p + 1) * HID + c0]) = make_float2(y01, y11);
    }
    __syncthreads();                                               // (3)

    // ---- gather1 (post-GEMM, linearity) + folded bias ----------------------
    ull pv[N_NODES];
    {
        const float2 bc = *reinterpret_cast<const float2*>(&b1c_g[c0]);
        const ull binit = pack2(bc.x, bc.y);
        #pragma unroll
        for (int i = 0; i < N_NODES; i++) {
            ull s = binit;
            const int* nb = &nbrs[i * KNN];
            #pragma unroll
            for (int j = 0; j < KNN; j++) {
                ull v = *reinterpret_cast<const ull*>(&nm[nb[j] * HID + c0]);
                ADD2(s, v);
            }
            pv[i] = s;
        }
    }
    __syncthreads();                                               // (4) gather reads done

    // ---- LN1: stage p node-major, warp-parallel stats ----------------------
    float p0[N_NODES], p1[N_NODES];
    #pragma unroll
    for (int i = 0; i < N_NODES; i++) {
        unpack2(pv[i], p0[i], p1[i]);
        *reinterpret_cast<float2*>(&nm[i * HID + c0]) = make_float2(p0[i], p1[i]);
    }
    __syncthreads();                                               // (5)
    #pragma unroll
    for (int ii = 0; ii < 10; ii++) {
        const int i = warp * 10 + ii;
        float v0 = nm[i * HID + lane];
        float v1 = nm[i * HID + lane + 32];
        float v2 = nm[i * HID + lane + 64];
        float v3 = nm[i * HID + lane + 96];
        float s = (v0 + v1) + (v2 + v3);
        float q = fmaf(v0, v0, fmaf(v1, v1, fmaf(v2, v2, v3 * v3)));
        #pragma unroll
        for (int off = 16; off; off >>= 1) {
            s += __shfl_xor_sync(0xffffffffu, s, off);
            q += __shfl_xor_sync(0xffffffffu, q, off);
        }
        if (lane == 0) {
            float m = s * (1.0f / HID);
            mean_s[i] = m;
            rstd_s[i] = rsqrtf(fmaf(-m, m, q * (1.0f / HID)) + LN_EPS);
        }
    }
    __syncthreads();                                               // (6)

    // ---- normalize + gelu -> h (regs), write k-major for GEMM2 -------------
    float h0[N_NODES], h1[N_NODES];
    {
        const float2 g1p  = *reinterpret_cast<const float2*>(&g1[c0]);
        const float2 be1p = *reinterpret_cast<const float2*>(&be1[c0]);
        #pragma unroll
        for (int i = 0; i < N_NODES; i++) {
            const float m = mean_s[i], r = rstd_s[i];
            h0[i] = gelu_exact(fmaf((p0[i] - m) * r, g1p.x, be1p.x));
            h1[i] = gelu_exact(fmaf((p1[i] - m) * r, g1p.y, be1p.y));
            km[c0 * N_NODES + i]       = h0[i];
            km[(c0 + 1) * N_NODES + i] = h1[i];
        }
    }
    __syncthreads();                                               // (7)

    // ---- GEMM2: z = h @ w2 (K=128), channels c0,c0+1 -----------------------
    #pragma unroll
    for (int p = 0; p < N_NODES / 2; p++) { a0[p] = 0ull; a1[p] = 0ull; }
    {
        const float2* wc = reinterpret_cast<const float2*>(w2) + t;  // w2[k][c0..c0+1]
        #pragma unroll 4
        for (int k = 0; k < HID; k++) {
            const float2 w = __ldg(wc + (size_t)k * (HID / 2));
            const ull wp0 = splat2(w.x), wp1 = splat2(w.y);
            const ulonglong2* row = reinterpret_cast<const ulonglong2*>(&km[k * N_NODES]);
            #pragma unroll
            for (int p = 0; p < 5; p++) {
                ulonglong2 hv = row[p];
                FMA2(a0[2 * p],     hv.x, wp0); FMA2(a0[2 * p + 1], hv.y, wp0);
                FMA2(a1[2 * p],     hv.x, wp1); FMA2(a1[2 * p + 1], hv.y, wp1);
            }
        }
    }
    // stage z node-major (nm is dead since sync (6))
    #pragma unroll
    for (int p = 0; p < N_NODES / 2; p++) {
        float z00, z01, z10, z11;
        unpack2(a0[p], z00, z01);
        unpack2(a1[p], z10, z11);
        *reinterpret_cast<float2*>(&nm[(2 * p)     * HID + c0]) = make_float2(z00, z10);
        *reinterpret_cast<float2*>(&nm[(2 * p + 1) * HID + c0]) = make_float2(z01, z11);
    }
    __syncthreads();                                               // (8)

    // ---- gather2 + b2 ------------------------------------------------------
    {
        const float2 bc = *reinterpret_cast<const float2*>(&b2[c0]);
        const ull binit = pack2(bc.x, bc.y);
        #pragma unroll
        for (int i = 0; i < N_NODES; i++) {
            ull s = binit;
            const int* nb = &nbrs[i * KNN];
            #pragma unroll
            for (int j = 0; j < KNN; j++) {
                ull v = *reinterpret_cast<const ull*>(&nm[nb[j] * HID + c0]);
                ADD2(s, v);
            }
            pv[i] = s;
        }
    }
    __syncthreads();                                               // (9)

    // ---- LN2 stats ---------------------------------------------------------
    #pragma unroll
    for (int i = 0; i < N_NODES; i++) {
        unpack2(pv[i], p0[i], p1[i]);
        *reinterpret_cast<float2*>(&nm[i * HID + c0]) = make_float2(p0[i], p1[i]);
    }
    __syncthreads();                                               // (10)
    #pragma unroll
    for (int ii = 0; ii < 10; ii++) {
        const int i = warp * 10 + ii;
        float v0 = nm[i * HID + lane];
        float v1 = nm[i * HID + lane + 32];
        float v2 = nm[i * HID + lane + 64];
        float v3 = nm[i * HID + lane + 96];
        float s = (v0 + v1) + (v2 + v3);
        float q = fmaf(v0, v0, fmaf(v1, v1, fmaf(v2, v2, v3 * v3)));
        #pragma unroll
        for (int off = 16; off; off >>= 1) {
            s += __shfl_xor_sync(0xffffffffu, s, off);
            q += __shfl_xor_sync(0xffffffffu, q, off);
        }
        if (lane == 0) {
            float m = s * (1.0f / HID);
            mean_s[i] = m;
            rstd_s[i] = rsqrtf(fmaf(-m, m, q * (1.0f / HID)) + LN_EPS);
        }
    }
    __syncthreads();                                               // (11)

    // ---- residual + gelu + max over nodes ----------------------------------
    {
        const float2 g2p  = *reinterpret_cast<const float2*>(&g2[c0]);
        const float2 be2p = *reinterpret_cast<const float2*>(&be2[c0]);
        float mx0 = -CUDART_INF_F, mx1 = -CUDART_INF_F;
        #pragma unroll
        for (int i = 0; i < N_NODES; i++) {
            const float m = mean_s[i], r = rstd_s[i];
            float v0 = fmaf((p0[i] - m) * r, g2p.x, be2p.x);
            float v1 = fmaf((p1[i] - m) * r, g2p.y, be2p.y);
            mx0 = fmaxf(mx0, gelu_exact(h0[i] + v0));
            mx1 = fmaxf(mx1, gelu_exact(h1[i] + v1));
        }
        *reinterpret_cast<float2*>(&out[(size_t)b * HID + c0]) = make_float2(mx0, mx1);
    }
}

extern "C" void kernel_launch(void* const* d_in, const int* in_sizes, int n_in,
                              void* d_out, int out_size)
{
    const float* x_all   = (const float*)d_in[0];
    const float* w_embed = (const float*)d_in[1];
    const float* b_embed = (const float*)d_in[2];
    const float* w1      = (const float*)d_in[3];
    const float* b1      = (const float*)d_in[4];
    const float* w2      = (const float*)d_in[5];
    const float* b2      = (const float*)d_in[6];
    const float* g1      = (const float*)d_in[7];
    const float* be1     = (const float*)d_in[8];
    const float* g2      = (const float*)d_in[9];
    const float* be2     = (const float*)d_in[10];
    float* out = (float*)d_out;

    const int B = in_sizes[0] / (N_NODES * IN_DIM);

    prep_kernel<<<1, HID>>>(w_embed, b_embed, w1, b1);
    hbond_gnn_kernel<<<B, 64>>>(x_all, w2, b2, g1, be1, g2, be2, out);
}

// round 12
// speedup vs baseline: 2.2686x; 1.0150x over previous
#include <cuda_runtime.h>
#include <cstdint>
#include <math_constants.h>

#define N_NODES 20
#define IN_DIM  9
#define HID     128
#define KNN     5
#define LN_EPS  1e-5f

typedef unsigned long long ull;

// Precomputed folded first layer: W1c = w_embed @ w1  (9x128),
// b1c = 5*(b_embed @ w1) + b1  (adjacency rows sum to exactly KNN=5).
__device__ float W1c_g[IN_DIM * HID];
__device__ float b1c_g[HID];

__device__ __forceinline__ float gelu_exact(float x) {
    return 0.5f * x * (1.0f + erff(x * 0.70710678118654752440f));
}
__device__ __forceinline__ ull splat2(float v) {
    ull r; asm("mov.b64 %0, {%1, %1};" : "=l"(r) : "r"(__float_as_uint(v))); return r;
}
__device__ __forceinline__ ull pack2(float a, float b) {
    ull r; asm("mov.b64 %0, {%1, %2};" : "=l"(r)
               : "r"(__float_as_uint(a)), "r"(__float_as_uint(b))); return r;
}
__device__ __forceinline__ void unpack2(ull v, float& a, float& b) {
    unsigned lo, hi; asm("mov.b64 {%0,%1}, %2;" : "=r"(lo), "=r"(hi) : "l"(v));
    a = __uint_as_float(lo); b = __uint_as_float(hi);
}
#define FMA2(acc, h, w) asm("fma.rn.f32x2 %0, %1, %2, %0;" : "+l"(acc) : "l"(h), "l"(w))
#define ADD2(acc, v)    asm("add.rn.f32x2 %0, %1, %0;"     : "+l"(acc) : "l"(v))

// ---------------------------------------------------------------------------
// Prep: fold embed into GEMM1. One tiny CTA, runs once per launch.
// ---------------------------------------------------------------------------
__global__ void prep_kernel(const float* __restrict__ we, const float* __restrict__ be,
                            const float* __restrict__ w1, const float* __restrict__ b1)
{
    const int c = threadIdx.x;            // 0..127
    float acc[IN_DIM];
    #pragma unroll
    for (int q = 0; q < IN_DIM; q++) acc[q] = 0.0f;
    float bb = 0.0f;
    for (int m = 0; m < HID; m++) {
        const float w = w1[m * HID + c];
        #pragma unroll
        for (int q = 0; q < IN_DIM; q++) acc[q] = fmaf(we[q * HID + m], w, acc[q]);
        bb = fmaf(be[m], w, bb);
    }
    #pragma unroll
    for (int q = 0; q < IN_DIM; q++) W1c_g[q * HID + c] = acc[q];
    b1c_g[c] = fmaf(5.0f, bb, b1[c]);
}

// One GEMM2 k-step. km rows are chunk-rotated: physical 16B chunk j of row k
// holds logical chunk q = (j - k%5) mod 5 (nodes 4q..4q+3). U = k % 5 is a
// compile-time template arg, so the inverse rotation is a static accumulator
// permutation: identical LDS.128 pattern, zero extra instructions.
template<int U>
__device__ __forceinline__ void gemm2_step(const float2* __restrict__ wc,
                                           const float* km, ull* a0, ull* a1, int k)
{
    const float2 w = __ldg(wc + (size_t)k * (HID / 2));
    const ull wp0 = splat2(w.x), wp1 = splat2(w.y);
    const ulonglong2* row = reinterpret_cast<const ulonglong2*>(km + k * N_NODES);
    #pragma unroll
    for (int j = 0; j < 5; j++) {
        const int q = (j + 5 - U) % 5;          // compile-time after unroll
        ulonglong2 hv = row[j];
        FMA2(a0[2 * q],     hv.x, wp0); FMA2(a0[2 * q + 1], hv.y, wp0);
        FMA2(a1[2 * q],     hv.x, wp1); FMA2(a1[2 * q + 1], hv.y, wp1);
    }
}

// ---------------------------------------------------------------------------
// Main: one CTA per graph, 64 threads; thread t owns channels (2t, 2t+1).
// Gathers commuted to after each GEMM (adjacency acts on nodes, weights on
// channels -> they commute); gathers read node-major float2 (conflict-free).
// km stores use a per-row chunk rotation: 8-way bank conflict -> <=2-way.
// ---------------------------------------------------------------------------
__global__ void __launch_bounds__(64, 8)
hbond_gnn_kernel(const float* __restrict__ x_all,
                 const float* __restrict__ w2,
                 const float* __restrict__ b2,
                 const float* __restrict__ g1,
                 const float* __restrict__ be1,
                 const float* __restrict__ g2,
                 const float* __restrict__ be2,
                 float* __restrict__ out)
{
    const int b    = blockIdx.x;
    const int t    = threadIdx.x;          // 0..63
    const int warp = t >> 5, lane = t & 31;
    const int c0   = 2 * t;                // channel pair (c0, c0+1)

    __shared__ __align__(16) float nm[N_NODES * HID];    // node-major staging
    __shared__ __align__(16) float km[HID * N_NODES];    // k-major GEMM2 operand (rotated chunks)
    __shared__ __align__(16) float xk[IN_DIM * N_NODES]; // x^T (k-major, 9x20)
    __shared__ float xs[N_NODES * IN_DIM];
    __shared__ int   nbrs[N_NODES * KNN];
    __shared__ float mean_s[N_NODES];
    __shared__ float rstd_s[N_NODES];

    // ---- load graph input --------------------------------------------------
    const float* xg = x_all + (size_t)b * (N_NODES * IN_DIM);
    for (int idx = t; idx < N_NODES * IN_DIM; idx += 64) xs[idx] = xg[idx];
    __syncthreads();                                               // (1)

    // ---- transpose x to k-major --------------------------------------------
    for (int idx = t; idx < N_NODES * IN_DIM; idx += 64) {
        int i = idx / IN_DIM, q = idx % IN_DIM;
        xk[q * N_NODES + i] = xs[idx];
    }
    // ---- kNN (threads 0..19, one node each) --------------------------------
    if (t < N_NODES) {
        const float px = xs[t * IN_DIM + 6];
        const float py = xs[t * IN_DIM + 7];
        const float pz = xs[t * IN_DIM + 8];
        float d2[N_NODES];
        #pragma unroll
        for (int j = 0; j < N_NODES; j++) {
            float dx = px - xs[j * IN_DIM + 6];
            float dy = py - xs[j * IN_DIM + 7];
            float dz = pz - xs[j * IN_DIM + 8];
            d2[j] = fmaf(dx, dx, fmaf(dy, dy, dz * dz));
        }
        unsigned mask = 0;
        #pragma unroll
        for (int m = 0; m < KNN; m++) {
            float best = CUDART_INF_F; int bj = 0;
            #pragma unroll
            for (int j = 0; j < N_NODES; j++) {
                // strict < keeps lowest index among ties (top_k semantics)
                if (!((mask >> j) & 1u) && d2[j] < best) { best = d2[j]; bj = j; }
            }
            mask |= 1u << bj;
            nbrs[t * KNN + m] = bj;
        }
    }
    __syncthreads();                                               // (2)

    // ---- GEMM1 (K=9, folded embed): y = x @ W1c, channels c0,c0+1 ----------
    ull a0[N_NODES / 2], a1[N_NODES / 2];     // node-pair packed, per channel
    #pragma unroll
    for (int p = 0; p < N_NODES / 2; p++) { a0[p] = 0ull; a1[p] = 0ull; }
    #pragma unroll
    for (int q = 0; q < IN_DIM; q++) {
        const float2 w = *reinterpret_cast<const float2*>(&W1c_g[q * HID + c0]);
        const ull wp0 = splat2(w.x), wp1 = splat2(w.y);
        const ulonglong2* row = reinterpret_cast<const ulonglong2*>(&xk[q * N_NODES]);
        #pragma unroll
        for (int p = 0; p < 5; p++) {
            ulonglong2 hv = row[p];
            FMA2(a0[2 * p],     hv.x, wp0); FMA2(a0[2 * p + 1], hv.y, wp0);
            FMA2(a1[2 * p],     hv.x, wp1); FMA2(a1[2 * p + 1], hv.y, wp1);
        }
    }
    // stage y node-major as float2 {c0, c0+1}
    #pragma unroll
    for (int p = 0; p < N_NODES / 2; p++) {
        float y00, y01, y10, y11;
        unpack2(a0[p], y00, y01);   // channel c0, nodes 2p, 2p+1
        unpack2(a1[p], y10, y11);   // channel c0+1
        *reinterpret_cast<float2*>(&nm[(2 * p)     * HID + c0]) = make_float2(y00, y10);
        *reinterpret_cast<float2*>(&nm[(2 * p + 1) * HID + c0]) = make_float2(y01, y11);
    }
    __syncthreads();                                               // (3)

    // ---- gather1 (post-GEMM, linearity) + folded bias ----------------------
    ull pv[N_NODES];
    {
        const float2 bc = *reinterpret_cast<const float2*>(&b1c_g[c0]);
        const ull binit = pack2(bc.x, bc.y);
        #pragma unroll
        for (int i = 0; i < N_NODES; i++) {
            ull s = binit;
            const int* nb = &nbrs[i * KNN];
            #pragma unroll
            for (int j = 0; j < KNN; j++) {
                ull v = *reinterpret_cast<const ull*>(&nm[nb[j] * HID + c0]);
                ADD2(s, v);
            }
            pv[i] = s;
        }
    }
    __syncthreads();                                               // (4) gather reads done

    // ---- LN1: stage p node-major, warp-parallel stats ----------------------
    float p0[N_NODES], p1[N_NODES];
    #pragma unroll
    for (int i = 0; i < N_NODES; i++) {
        unpack2(pv[i], p0[i], p1[i]);
        *reinterpret_cast<float2*>(&nm[i * HID + c0]) = make_float2(p0[i], p1[i]);
    }
    __syncthreads();                                               // (5)
    #pragma unroll
    for (int ii = 0; ii < 10; ii++) {
        const int i = warp * 10 + ii;
        float v0 = nm[i * HID + lane];
        float v1 = nm[i * HID + lane + 32];
        float v2 = nm[i * HID + lane + 64];
        float v3 = nm[i * HID + lane + 96];
        float s = (v0 + v1) + (v2 + v3);
        float q = fmaf(v0, v0, fmaf(v1, v1, fmaf(v2, v2, v3 * v3)));
        #pragma unroll
        for (int off = 16; off; off >>= 1) {
            s += __shfl_xor_sync(0xffffffffu, s, off);
            q += __shfl_xor_sync(0xffffffffu, q, off);
        }
        if (lane == 0) {
            float m = s * (1.0f / HID);
            mean_s[i] = m;
            rstd_s[i] = rsqrtf(fmaf(-m, m, q * (1.0f / HID)) + LN_EPS);
        }
    }
    __syncthreads();                                               // (6)

    // ---- normalize + gelu -> h (regs), write rotated k-major for GEMM2 -----
    float h0[N_NODES], h1[N_NODES];
    {
        const float2 g1p  = *reinterpret_cast<const float2*>(&g1[c0]);
        const float2 be1p = *reinterpret_cast<const float2*>(&be1[c0]);
        // chunk rotation offsets for rows c0, c0+1 (hoisted out of the i loop)
        const int rot0 = c0 % 5, rot1 = (c0 + 1) % 5;
        int off0[5], off1[5];
        #pragma unroll
        for (int q = 0; q < 5; q++) {
            int s0 = q + rot0; if (s0 >= 5) s0 -= 5;
            int s1 = q + rot1; if (s1 >= 5) s1 -= 5;
            off0[q] = s0 * 4;
            off1[q] = s1 * 4;
        }
        #pragma unroll
        for (int i = 0; i < N_NODES; i++) {
            const float m = mean_s[i], r = rstd_s[i];
            h0[i] = gelu_exact(fmaf((p0[i] - m) * r, g1p.x, be1p.x));
            h1[i] = gelu_exact(fmaf((p1[i] - m) * r, g1p.y, be1p.y));
            km[c0 * N_NODES       + off0[i >> 2] + (i & 3)] = h0[i];
            km[(c0 + 1) * N_NODES + off1[i >> 2] + (i & 3)] = h1[i];
        }
    }
    __syncthreads();                                               // (7)

    // ---- GEMM2: z = h @ w2 (K=128), channels c0,c0+1 -----------------------
    #pragma unroll
    for (int p = 0; p < N_NODES / 2; p++) { a0[p] = 0ull; a1[p] = 0ull; }
    {
        const float2* wc = reinterpret_cast<const float2*>(w2) + t;  // w2[k][c0..c0+1]
        for (int k0 = 0; k0 < 125; k0 += 5) {       // 125 = 25*5, k0 % 5 == 0
            gemm2_step<0>(wc, km, a0, a1, k0);
            gemm2_step<1>(wc, km, a0, a1, k0 + 1);
            gemm2_step<2>(wc, km, a0, a1, k0 + 2);
            gemm2_step<3>(wc, km, a0, a1, k0 + 3);
            gemm2_step<4>(wc, km, a0, a1, k0 + 4);
        }
        gemm2_step<0>(wc, km, a0, a1, 125);         // 125 % 5 == 0
        gemm2_step<1>(wc, km, a0, a1, 126);
        gemm2_step<2>(wc, km, a0, a1, 127);
    }
    // stage z node-major (nm is dead since sync (6))
    #pragma unroll
    for (int p = 0; p < N_NODES / 2; p++) {
        float z00, z01, z10, z11;
        unpack2(a0[p], z00, z01);
        unpack2(a1[p], z10, z11);
        *reinterpret_cast<float2*>(&nm[(2 * p)     * HID + c0]) = make_float2(z00, z10);
        *reinterpret_cast<float2*>(&nm[(2 * p + 1) * HID + c0]) = make_float2(z01, z11);
    }
    __syncthreads();                                               // (8)

    // ---- gather2 + b2 ------------------------------------------------------
    {
        const float2 bc = *reinterpret_cast<const float2*>(&b2[c0]);
        const ull binit = pack2(bc.x, bc.y);
        #pragma unroll
        for (int i = 0; i < N_NODES; i++) {
            ull s = binit;
            const int* nb = &nbrs[i * KNN];
            #pragma unroll
            for (int j = 0; j < KNN; j++) {
                ull v = *reinterpret_cast<const ull*>(&nm[nb[j] * HID + c0]);
                ADD2(s, v);
            }
            pv[i] = s;
        }
    }
    __syncthreads();                                               // (9)

    // ---- LN2 stats ---------------------------------------------------------
    #pragma unroll
    for (int i = 0; i < N_NODES; i++) {
        unpack2(pv[i], p0[i], p1[i]);
        *reinterpret_cast<float2*>(&nm[i * HID + c0]) = make_float2(p0[i], p1[i]);
    }
    __syncthreads();                                               // (10)
    #pragma unroll
    for (int ii = 0; ii < 10; ii++) {
        const int i = warp * 10 + ii;
        float v0 = nm[i * HID + lane];
        float v1 = nm[i * HID + lane + 32];
        float v2 = nm[i * HID + lane + 64];
        float v3 = nm[i * HID + lane + 96];
        float s = (v0 + v1) + (v2 + v3);
        float q = fmaf(v0, v0, fmaf(v1, v1, fmaf(v2, v2, v3 * v3)));
        #pragma unroll
        for (int off = 16; off; off >>= 1) {
            s += __shfl_xor_sync(0xffffffffu, s, off);
            q += __shfl_xor_sync(0xffffffffu, q, off);
        }
        if (lane == 0) {
            float m = s * (1.0f / HID);
            mean_s[i] = m;
            rstd_s[i] = rsqrtf(fmaf(-m, m, q * (1.0f / HID)) + LN_EPS);
        }
    }
    __syncthreads();                                               // (11)

    // ---- residual + gelu + max over nodes ----------------------------------
    {
        const float2 g2p  = *reinterpret_cast<const float2*>(&g2[c0]);
        const float2 be2p = *reinterpret_cast<const float2*>(&be2[c0]);
        float mx0 = -CUDART_INF_F, mx1 = -CUDART_INF_F;
        #pragma unroll
        for (int i = 0; i < N_NODES; i++) {
            const float m = mean_s[i], r = rstd_s[i];
            float v0 = fmaf((p0[i] - m) * r, g2p.x, be2p.x);
            float v1 = fmaf((p1[i] - m) * r, g2p.y, be2p.y);
            mx0 = fmaxf(mx0, gelu_exact(h0[i] + v0));
            mx1 = fmaxf(mx1, gelu_exact(h1[i] + v1));
        }
        *reinterpret_cast<float2*>(&out[(size_t)b * HID + c0]) = make_float2(mx0, mx1);
    }
}

extern "C" void kernel_launch(void* const* d_in, const int* in_sizes, int n_in,
                              void* d_out, int out_size)
{
    const float* x_all   = (const float*)d_in[0];
    const float* w_embed = (const float*)d_in[1];
    const float* b_embed = (const float*)d_in[2];
    const float* w1      = (const float*)d_in[3];
    const float* b1      = (const float*)d_in[4];
    const float* w2      = (const float*)d_in[5];
    const float* b2      = (const float*)d_in[6];
    const float* g1      = (const float*)d_in[7];
    const float* be1     = (const float*)d_in[8];
    const float* g2      = (const float*)d_in[9];
    const float* be2     = (const float*)d_in[10];
    float* out = (float*)d_out;

    const int B = in_sizes[0] / (N_NODES * IN_DIM);

    prep_kernel<<<1, HID>>>(w_embed, b_embed, w1, b1);
    hbond_gnn_kernel<<<B, 64>>>(x_all, w2, b2, g1, be1, g2, be2, out);
}